// round 9
// baseline (speedup 1.0000x reference)
#include <cuda_runtime.h>
#include <stdint.h>

// Haar DWT level-1: x (8,32,512,512) fp32 -> (LL,LH,HL,HH) each (8,32,256,256)
// d_out layout: [LL | LH | HL | HH], each band 16,777,216 floats.
//
// Persistent single-wave variant: grid = 304 CTAs (152 SMs x 2 resident CTAs
// of 1024 threads), grid-stride loop (~27 items/thread). Eliminates ~27 wave
// transitions that can starve DRAM at wave boundaries. Per-item work identical
// to best-measured R7 structure (2x LDG.128 + 4x STG.64, default policy).

#define H_IN   512
#define W_IN   512
#define H_OUT  256
#define W_OUT  256
#define N_IMG  256                           // 8*32
#define BAND_ELEMS (N_IMG * H_OUT * W_OUT)   // 16,777,216
#define PAIRS_PER_ROW (W_OUT / 2)            // 128
#define TOTAL_ITEMS (N_IMG * H_OUT * PAIRS_PER_ROW)   // 8,388,608

__global__ __launch_bounds__(1024)
void haar_dwt_kernel(const float* __restrict__ x, float* __restrict__ out) {
    const float q = 0.25f;
    float2* outp = reinterpret_cast<float2*>(out);
    const size_t band2 = BAND_ELEMS / 2;   // band stride in float2 units

    unsigned stride = gridDim.x * blockDim.x;

    for (unsigned idx = blockIdx.x * blockDim.x + threadIdx.x;
         idx < TOTAL_ITEMS; idx += stride) {

        unsigned px  = idx & (PAIRS_PER_ROW - 1);          // 0..127
        unsigned t   = idx >> 7;                            // img*256 + oy
        unsigned oy  = t & (H_OUT - 1);                     // 0..255
        unsigned img = t >> 8;                              // 0..255

        const float* base = x + ((size_t)img * H_IN + (size_t)(2 * oy)) * W_IN + 4 * px;
        float4 r0 = *reinterpret_cast<const float4*>(base);          // row 2oy
        float4 r1 = *reinterpret_cast<const float4*>(base + W_IN);   // row 2oy+1

        // Pair 0: a=r0.x b=r0.y c=r1.x d=r1.y ; Pair 1: a=r0.z b=r0.w c=r1.z d=r1.w
        float s0a = r0.x + r0.y, s1a = r1.x + r1.y;
        float d0a = r0.y - r0.x, d1a = r1.y - r1.x;
        float s0b = r0.z + r0.w, s1b = r1.z + r1.w;
        float d0b = r0.w - r0.z, d1b = r1.w - r1.z;

        float2 ll = make_float2(q * (s0a + s1a), q * (s0b + s1b));   //  a+b+c+d
        float2 lh = make_float2(q * (s1a - s0a), q * (s1b - s0b));   // -a-b+c+d
        float2 hl = make_float2(q * (d0a + d1a), q * (d0b + d1b));   // -a+b-c+d
        float2 hh = make_float2(q * (d1a - d0a), q * (d1b - d0b));   //  a-b-c+d

        size_t o = ((size_t)img * H_OUT + oy) * PAIRS_PER_ROW + px;

        outp[o]             = ll;
        outp[o + band2]     = lh;
        outp[o + 2 * band2] = hl;
        outp[o + 3 * band2] = hh;
    }
}

extern "C" void kernel_launch(void* const* d_in, const int* in_sizes, int n_in,
                              void* d_out, int out_size) {
    const float* x = (const float*)d_in[0];
    float* out = (float*)d_out;

    // One wave: 152 SMs x 2 CTAs (1024 thr each, 2048 thr/SM occupancy cap).
    const unsigned block = 1024;
    const unsigned grid = 304;

    haar_dwt_kernel<<<grid, block>>>(x, out);
}

// round 10
// speedup vs baseline: 1.1116x; 1.1116x over previous
#include <cuda_runtime.h>
#include <stdint.h>

// Haar DWT level-1: x (8,32,512,512) fp32 -> (LL,LH,HL,HH) each (8,32,256,256)
// d_out layout: [LL | LH | HL | HH], each band 16,777,216 floats.
//
// FINAL (best measured, R7): one item per thread, 2x LDG.128 + 4x STG.64,
// block=1024, 20 regs, default cache policy. 80.4 us bench / 74.6 us kernel.
//
// Roofline closure: pinned at the DRAM mixed-R/W ceiling (6.54 TB/s, 82.5% of
// 8 TB/s spec). Traffic = 537 MB = one-touch information floor. Measured
// neutral-or-worse: per-thread MLP 2/4/8, store width 64/128b, block
// 256/512/1024, occupancy 48-94%, cache policy default/.cs/.wt, persistent
// single-wave grid-stride (regressed to 80 us kernel: loop-carried dependency
// caps in-flight loads; flat grid keeps memory queues deeper).

#define H_IN   512
#define W_IN   512
#define H_OUT  256
#define W_OUT  256
#define N_IMG  256                           // 8*32
#define BAND_ELEMS (N_IMG * H_OUT * W_OUT)   // 16,777,216
#define PAIRS_PER_ROW (W_OUT / 2)            // 128

__global__ __launch_bounds__(1024)
void haar_dwt_kernel(const float* __restrict__ x, float* __restrict__ out) {
    // One thread per (img, oy, px): total = 256*256*128 = 8,388,608.
    unsigned idx = blockIdx.x * blockDim.x + threadIdx.x;

    unsigned px  = idx & (PAIRS_PER_ROW - 1);          // 0..127
    unsigned t   = idx >> 7;                            // img*256 + oy
    unsigned oy  = t & (H_OUT - 1);                     // 0..255
    unsigned img = t >> 8;                              // 0..255

    const float* base = x + ((size_t)img * H_IN + (size_t)(2 * oy)) * W_IN + 4 * px;
    float4 r0 = *reinterpret_cast<const float4*>(base);          // row 2oy
    float4 r1 = *reinterpret_cast<const float4*>(base + W_IN);   // row 2oy+1

    const float q = 0.25f;

    // Pair 0: a=r0.x b=r0.y c=r1.x d=r1.y ; Pair 1: a=r0.z b=r0.w c=r1.z d=r1.w
    float s0a = r0.x + r0.y, s1a = r1.x + r1.y;
    float d0a = r0.y - r0.x, d1a = r1.y - r1.x;
    float s0b = r0.z + r0.w, s1b = r1.z + r1.w;
    float d0b = r0.w - r0.z, d1b = r1.w - r1.z;

    float2 ll = make_float2(q * (s0a + s1a), q * (s0b + s1b));   //  a+b+c+d
    float2 lh = make_float2(q * (s1a - s0a), q * (s1b - s0b));   // -a-b+c+d
    float2 hl = make_float2(q * (d0a + d1a), q * (d0b + d1b));   // -a+b-c+d
    float2 hh = make_float2(q * (d1a - d0a), q * (d1b - d0b));   //  a-b-c+d

    size_t o = ((size_t)img * H_OUT + oy) * PAIRS_PER_ROW + px;

    float2* outp = reinterpret_cast<float2*>(out);
    const size_t band2 = BAND_ELEMS / 2;   // band stride in float2 units
    outp[o]             = ll;
    outp[o + band2]     = lh;
    outp[o + 2 * band2] = hl;
    outp[o + 3 * band2] = hh;
}

extern "C" void kernel_launch(void* const* d_in, const int* in_sizes, int n_in,
                              void* d_out, int out_size) {
    const float* x = (const float*)d_in[0];
    float* out = (float*)d_out;

    const unsigned total_threads = N_IMG * H_OUT * PAIRS_PER_ROW;  // 8,388,608
    const unsigned block = 1024;
    const unsigned grid = total_threads / block;                   // 8192

    haar_dwt_kernel<<<grid, block>>>(x, out);
}

// round 11
// speedup vs baseline: 1.1227x; 1.0100x over previous
#include <cuda_runtime.h>
#include <stdint.h>

// Haar DWT level-1: x (8,32,512,512) fp32 -> (LL,LH,HL,HH) each (8,32,256,256)
// d_out layout: [LL | LH | HL | HH], each band 16,777,216 floats.
//
// R7 structure (best measured: one item/thread, 2x LDG.128 + 4x STG.64,
// block=1024, default policy) + per-warp rotated band store order:
// warp w stores bands in order (w, w+1, w+2, w+3) mod 4, so the chip's
// instantaneous write stream spans all four 64MB band regions instead of
// sweeping them one at a time -> more DRAM bank-group/row diversity for
// write bursts. Coalescing unchanged (256B contiguous per warp per band).

#define H_IN   512
#define W_IN   512
#define H_OUT  256
#define W_OUT  256
#define N_IMG  256                           // 8*32
#define BAND_ELEMS (N_IMG * H_OUT * W_OUT)   // 16,777,216
#define PAIRS_PER_ROW (W_OUT / 2)            // 128

__global__ __launch_bounds__(1024)
void haar_dwt_kernel(const float* __restrict__ x, float* __restrict__ out) {
    // One thread per (img, oy, px): total = 256*256*128 = 8,388,608.
    unsigned idx = blockIdx.x * blockDim.x + threadIdx.x;

    unsigned px  = idx & (PAIRS_PER_ROW - 1);          // 0..127
    unsigned t   = idx >> 7;                            // img*256 + oy
    unsigned oy  = t & (H_OUT - 1);                     // 0..255
    unsigned img = t >> 8;                              // 0..255

    const float* base = x + ((size_t)img * H_IN + (size_t)(2 * oy)) * W_IN + 4 * px;
    float4 r0 = *reinterpret_cast<const float4*>(base);          // row 2oy
    float4 r1 = *reinterpret_cast<const float4*>(base + W_IN);   // row 2oy+1

    const float q = 0.25f;

    // Pair 0: a=r0.x b=r0.y c=r1.x d=r1.y ; Pair 1: a=r0.z b=r0.w c=r1.z d=r1.w
    float s0a = r0.x + r0.y, s1a = r1.x + r1.y;
    float d0a = r0.y - r0.x, d1a = r1.y - r1.x;
    float s0b = r0.z + r0.w, s1b = r1.z + r1.w;
    float d0b = r0.w - r0.z, d1b = r1.w - r1.z;

    float2 ll = make_float2(q * (s0a + s1a), q * (s0b + s1b));   //  a+b+c+d
    float2 lh = make_float2(q * (s1a - s0a), q * (s1b - s0b));   // -a-b+c+d
    float2 hl = make_float2(q * (d0a + d1a), q * (d0b + d1b));   // -a+b-c+d
    float2 hh = make_float2(q * (d1a - d0a), q * (d1b - d0b));   //  a-b-c+d

    size_t o = ((size_t)img * H_OUT + oy) * PAIRS_PER_ROW + px;

    float2* outp = reinterpret_cast<float2*>(out);
    const size_t band2 = BAND_ELEMS / 2;   // band stride in float2 units

    // Per-warp rotation of band store order.
    unsigned rot = (threadIdx.x >> 5) & 3;
#pragma unroll
    for (int k = 0; k < 4; k++) {
        unsigned b = (rot + k) & 3;
        float2 v = (b == 0) ? ll : (b == 1) ? lh : (b == 2) ? hl : hh;
        outp[o + (size_t)b * band2] = v;
    }
}

extern "C" void kernel_launch(void* const* d_in, const int* in_sizes, int n_in,
                              void* d_out, int out_size) {
    const float* x = (const float*)d_in[0];
    float* out = (float*)d_out;

    const unsigned total_threads = N_IMG * H_OUT * PAIRS_PER_ROW;  // 8,388,608
    const unsigned block = 1024;
    const unsigned grid = total_threads / block;                   // 8192

    haar_dwt_kernel<<<grid, block>>>(x, out);
}